// round 4
// baseline (speedup 1.0000x reference)
#include <cuda_runtime.h>

// Encoder: out[b,e] = relu( sum_i combined[b,i] * weight[b,i,e] )
// combined = [ features[nodes[b]] , mean_j features[neigh_idx[b,j]] ]  (256 dims)
// Shapes: features [100000,128] f32, weight [4096,256,128] f32,
//         nodes [4096] i32, neigh_idx [4096,10] i32, out [4096,128] f32.
//
// HBM-bound streaming kernel at the ~6.4TB/s achievable ceiling. Lever: bytes.
//  - features (51MB, reused via random gathers) -> L2 evict_last policy
//    (pins the table in the 126MB L2; gathers stay compulsory-only).
//  - weight (512MB, single-use stream)          -> L2 evict_first policy
//    (stream never displaces the pinned feature lines).
// sm_103a ptxas rejects the inline .L2::evict_* qualifier below 32B width,
// so we use createpolicy + ld.global.nc.L2::cache_hint instead.

#define FEAT 128
#define EMBED 128
#define TWO_FEAT 256
#define NUM_SAMPLE 10

__device__ __forceinline__ unsigned long long policy_evict_last() {
    unsigned long long p;
    asm volatile("createpolicy.fractional.L2::evict_last.b64 %0, 1.0;" : "=l"(p));
    return p;
}

__device__ __forceinline__ unsigned long long policy_evict_first() {
    unsigned long long p;
    asm volatile("createpolicy.fractional.L2::evict_first.b64 %0, 1.0;" : "=l"(p));
    return p;
}

__device__ __forceinline__ float ldg_keep(const float* p, unsigned long long pol) {
    float v;
    asm volatile("ld.global.nc.L2::cache_hint.f32 %0, [%1], %2;"
                 : "=f"(v) : "l"(p), "l"(pol));
    return v;
}

__device__ __forceinline__ float4 ldg_stream4(const float4* p, unsigned long long pol) {
    float4 v;
    asm volatile("ld.global.nc.L2::cache_hint.v4.f32 {%0,%1,%2,%3}, [%4], %5;"
                 : "=f"(v.x), "=f"(v.y), "=f"(v.z), "=f"(v.w) : "l"(p), "l"(pol));
    return v;
}

__global__ __launch_bounds__(128, 8)
void encoder_kernel(const float* __restrict__ features,
                    const float* __restrict__ weight,
                    const int*   __restrict__ nodes,
                    const int*   __restrict__ neigh,
                    float*       __restrict__ out)
{
    __shared__ float comb[TWO_FEAT];
    __shared__ float part[4][EMBED];

    const int b = blockIdx.x;
    const int t = threadIdx.x;          // 0..127
    const int warp = t >> 5;
    const int lane = t & 31;

    const unsigned long long pol_keep   = policy_evict_last();
    const unsigned long long pol_stream = policy_evict_first();

    const float4* __restrict__ Wb =
        reinterpret_cast<const float4*>(weight + (size_t)b * TWO_FEAT * EMBED);
    const int i0 = warp * 64;

    // ---- start the weight stream immediately (evict-first, single-use)
    float4 pre0 = ldg_stream4(&Wb[(size_t)(i0 + 0) * (EMBED / 4) + lane], pol_stream);
    float4 pre1 = ldg_stream4(&Wb[(size_t)(i0 + 1) * (EMBED / 4) + lane], pol_stream);
    float4 pre2 = ldg_stream4(&Wb[(size_t)(i0 + 2) * (EMBED / 4) + lane], pol_stream);
    float4 pre3 = ldg_stream4(&Wb[(size_t)(i0 + 3) * (EMBED / 4) + lane], pol_stream);

    // ---- Phase 1: build combined[256] in shared (coalesced 512B row loads,
    //      evict_last pins the feature table in L2)
    const int node = __ldg(&nodes[b]);
    float self_f = ldg_keep(&features[(size_t)node * FEAT + t], pol_keep);

    float msum = 0.0f;
    #pragma unroll
    for (int j = 0; j < NUM_SAMPLE; ++j) {
        const int nb = __ldg(&neigh[b * NUM_SAMPLE + j]);
        msum += ldg_keep(&features[(size_t)nb * FEAT + t], pol_keep);
    }
    comb[t]        = self_f;
    comb[FEAT + t] = msum * (1.0f / NUM_SAMPLE);
    __syncthreads();

    // ---- Phase 2: per-sample matvec, streaming weight[b] (128 KB/CTA)
    // warp w handles rows [w*64, w*64+64); lane covers e = 4*lane..4*lane+3.
    float4 accA = make_float4(0.f, 0.f, 0.f, 0.f);
    float4 accB = make_float4(0.f, 0.f, 0.f, 0.f);

    // consume prefetched rows 0..3
    {
        float c0 = comb[i0 + 0], c1 = comb[i0 + 1];
        float c2 = comb[i0 + 2], c3 = comb[i0 + 3];
        accA.x = fmaf(c0, pre0.x, accA.x); accA.y = fmaf(c0, pre0.y, accA.y);
        accA.z = fmaf(c0, pre0.z, accA.z); accA.w = fmaf(c0, pre0.w, accA.w);
        accB.x = fmaf(c1, pre1.x, accB.x); accB.y = fmaf(c1, pre1.y, accB.y);
        accB.z = fmaf(c1, pre1.z, accB.z); accB.w = fmaf(c1, pre1.w, accB.w);
        accA.x = fmaf(c2, pre2.x, accA.x); accA.y = fmaf(c2, pre2.y, accA.y);
        accA.z = fmaf(c2, pre2.z, accA.z); accA.w = fmaf(c2, pre2.w, accA.w);
        accB.x = fmaf(c3, pre3.x, accB.x); accB.y = fmaf(c3, pre3.y, accB.y);
        accB.z = fmaf(c3, pre3.z, accB.z); accB.w = fmaf(c3, pre3.w, accB.w);
    }

    #pragma unroll 8
    for (int k = 4; k < 64; k += 2) {
        const float  cA = comb[i0 + k];
        const float  cB = comb[i0 + k + 1];
        const float4 wA = ldg_stream4(&Wb[(size_t)(i0 + k)     * (EMBED / 4) + lane], pol_stream);
        const float4 wB = ldg_stream4(&Wb[(size_t)(i0 + k + 1) * (EMBED / 4) + lane], pol_stream);
        accA.x = fmaf(cA, wA.x, accA.x); accA.y = fmaf(cA, wA.y, accA.y);
        accA.z = fmaf(cA, wA.z, accA.z); accA.w = fmaf(cA, wA.w, accA.w);
        accB.x = fmaf(cB, wB.x, accB.x); accB.y = fmaf(cB, wB.y, accB.y);
        accB.z = fmaf(cB, wB.z, accB.z); accB.w = fmaf(cB, wB.w, accB.w);
    }

    float4 acc;
    acc.x = accA.x + accB.x;
    acc.y = accA.y + accB.y;
    acc.z = accA.z + accB.z;
    acc.w = accA.w + accB.w;

    // stash per-warp partials
    reinterpret_cast<float4*>(&part[warp][0])[lane] = acc;
    __syncthreads();

    // ---- reduce 4 warps, relu, store (coalesced 512B)
    const float v = part[0][t] + part[1][t] + part[2][t] + part[3][t];
    out[(size_t)b * EMBED + t] = fmaxf(v, 0.0f);
}

extern "C" void kernel_launch(void* const* d_in, const int* in_sizes, int n_in,
                              void* d_out, int out_size)
{
    const float* features = (const float*)d_in[0];
    const float* weight   = (const float*)d_in[1];
    const int*   nodes    = (const int*)d_in[2];
    const int*   neigh    = (const int*)d_in[3];
    float*       out      = (float*)d_out;

    const int batch = in_sizes[2];      // 4096 (nodes element count)
    encoder_kernel<<<batch, 128>>>(features, weight, nodes, neigh, out);
}

// round 5
// speedup vs baseline: 1.0208x; 1.0208x over previous
#include <cuda_runtime.h>

// Encoder: out[b,e] = relu( sum_i combined[b,i] * weight[b,i,e] )
// combined = [ features[nodes[b]] , mean_j features[neigh_idx[b,j]] ]  (256 dims)
// Shapes: features [100000,128] f32, weight [4096,256,128] f32,
//         nodes [4096] i32, neigh_idx [4096,10] i32, out [4096,128] f32.
//
// DRAM-bound streaming kernel. Bytes are already compulsory (~533MB); the
// remaining lever is achieved HBM bandwidth. This revision raises request
// density: 51-reg cap -> 10 CTAs/SM (40 warps, was 32) while keeping an
// 8-deep float4 load batch per warp.

#define FEAT 128
#define EMBED 128
#define TWO_FEAT 256
#define NUM_SAMPLE 10

__global__ __launch_bounds__(128, 10)
void encoder_kernel(const float* __restrict__ features,
                    const float* __restrict__ weight,
                    const int*   __restrict__ nodes,
                    const int*   __restrict__ neigh,
                    float*       __restrict__ out)
{
    __shared__ float comb[TWO_FEAT];
    __shared__ float part[4][EMBED];

    const int b = blockIdx.x;
    const int t = threadIdx.x;          // 0..127
    const int warp = t >> 5;
    const int lane = t & 31;

    // ---- Phase 1: build combined[256] in shared.
    // thread t owns feature dim t; every row load is a coalesced 512B segment.
    const int node = __ldg(&nodes[b]);
    float self_f = __ldg(&features[(size_t)node * FEAT + t]);

    float msum = 0.0f;
    #pragma unroll
    for (int j = 0; j < NUM_SAMPLE; ++j) {
        const int nb = __ldg(&neigh[b * NUM_SAMPLE + j]);
        msum += __ldg(&features[(size_t)nb * FEAT + t]);
    }
    comb[t]        = self_f;
    comb[FEAT + t] = msum * (1.0f / NUM_SAMPLE);
    __syncthreads();

    // ---- Phase 2: per-sample matvec, streaming weight[b] (128 KB/CTA).
    // warp w handles rows [w*64, w*64+64); lane covers e = 4*lane..4*lane+3.
    // __ldcs: weight is single-use, evict-first.
    const float4* __restrict__ Wb =
        reinterpret_cast<const float4*>(weight + (size_t)b * TWO_FEAT * EMBED);
    const int i0 = warp * 64;

    float4 accA = make_float4(0.f, 0.f, 0.f, 0.f);
    float4 accB = make_float4(0.f, 0.f, 0.f, 0.f);

    #pragma unroll 8
    for (int k = 0; k < 64; k += 2) {
        const float  cA = comb[i0 + k];
        const float  cB = comb[i0 + k + 1];
        const float4 wA = __ldcs(&Wb[(size_t)(i0 + k)     * (EMBED / 4) + lane]);
        const float4 wB = __ldcs(&Wb[(size_t)(i0 + k + 1) * (EMBED / 4) + lane]);
        accA.x = fmaf(cA, wA.x, accA.x); accA.y = fmaf(cA, wA.y, accA.y);
        accA.z = fmaf(cA, wA.z, accA.z); accA.w = fmaf(cA, wA.w, accA.w);
        accB.x = fmaf(cB, wB.x, accB.x); accB.y = fmaf(cB, wB.y, accB.y);
        accB.z = fmaf(cB, wB.z, accB.z); accB.w = fmaf(cB, wB.w, accB.w);
    }

    float4 acc;
    acc.x = accA.x + accB.x;
    acc.y = accA.y + accB.y;
    acc.z = accA.z + accB.z;
    acc.w = accA.w + accB.w;

    // stash per-warp partials
    reinterpret_cast<float4*>(&part[warp][0])[lane] = acc;
    __syncthreads();

    // ---- reduce 4 warps, relu, store (coalesced 512B)
    const float v = part[0][t] + part[1][t] + part[2][t] + part[3][t];
    out[(size_t)b * EMBED + t] = fmaxf(v, 0.0f);
}

extern "C" void kernel_launch(void* const* d_in, const int* in_sizes, int n_in,
                              void* d_out, int out_size)
{
    const float* features = (const float*)d_in[0];
    const float* weight   = (const float*)d_in[1];
    const int*   nodes    = (const int*)d_in[2];
    const int*   neigh    = (const int*)d_in[3];
    float*       out      = (float*)d_out;

    const int batch = in_sizes[2];      // 4096 (nodes element count)
    encoder_kernel<<<batch, 128>>>(features, weight, nodes, neigh, out);
}

// round 6
// speedup vs baseline: 1.0293x; 1.0084x over previous
#include <cuda_runtime.h>

// Encoder: out[b,e] = relu( sum_i combined[b,i] * weight[b,i,e] )
// combined = [ features[nodes[b]] , mean_j features[neigh_idx[b,j]] ]  (256 dims)
// Shapes: features [100000,128] f32, weight [4096,256,128] f32,
//         nodes [4096] i32, neigh_idx [4096,10] i32, out [4096,128] f32.
//
// DRAM-bound streaming kernel (~533MB compulsory). This revision removes the
// block-wide barrier between gather and stream: each warp produces exactly
// the comb[] slice it will consume, so warps 0/1 (self-feature slice, one
// gather row) start streaming weight immediately instead of waiting for the
// 10-row neighbor mean computed by warps 2/3.

#define FEAT 128
#define EMBED 128
#define TWO_FEAT 256
#define NUM_SAMPLE 10

__global__ __launch_bounds__(128, 10)
void encoder_kernel(const float* __restrict__ features,
                    const float* __restrict__ weight,
                    const int*   __restrict__ nodes,
                    const int*   __restrict__ neigh,
                    float*       __restrict__ out)
{
    __shared__ float comb[TWO_FEAT];
    __shared__ float part[4][EMBED];

    const int b = blockIdx.x;
    const int t = threadIdx.x;          // 0..127
    const int warp = t >> 5;
    const int lane = t & 31;

    // ---- Phase 1 (warp-local): warp w builds comb[64w .. 64w+64).
    //   warp 0 -> self dims [0,64)     warp 1 -> self dims [64,128)
    //   warp 2 -> mean dims [0,64)     warp 3 -> mean dims [64,128)
    // Each warp writes a float2 per lane (64 floats), then __syncwarp only.
    {
        const int dim0 = (warp & 1) * 64 + lane * 2;   // 2 contiguous dims per lane
        float2 v;
        if (warp < 2) {
            const int node = __ldg(&nodes[b]);
            v = *reinterpret_cast<const float2*>(&features[(size_t)node * FEAT + dim0]);
        } else {
            float sx = 0.0f, sy = 0.0f;
            #pragma unroll
            for (int j = 0; j < NUM_SAMPLE; ++j) {
                const int nb = __ldg(&neigh[b * NUM_SAMPLE + j]);
                const float2 f = *reinterpret_cast<const float2*>(
                    &features[(size_t)nb * FEAT + dim0]);
                sx += f.x; sy += f.y;
            }
            v.x = sx * (1.0f / NUM_SAMPLE);
            v.y = sy * (1.0f / NUM_SAMPLE);
        }
        *reinterpret_cast<float2*>(&comb[warp * 64 + lane * 2]) = v;
        __syncwarp();
    }

    // ---- Phase 2: per-sample matvec, streaming weight[b] (128 KB/CTA).
    // warp w handles rows [w*64, w*64+64) == exactly the comb slice it wrote.
    // lane covers e = 4*lane..4*lane+3. __ldcs: weight is single-use.
    const float4* __restrict__ Wb =
        reinterpret_cast<const float4*>(weight + (size_t)b * TWO_FEAT * EMBED);
    const int i0 = warp * 64;

    float4 accA = make_float4(0.f, 0.f, 0.f, 0.f);
    float4 accB = make_float4(0.f, 0.f, 0.f, 0.f);

    #pragma unroll 8
    for (int k = 0; k < 64; k += 2) {
        const float  cA = comb[i0 + k];
        const float  cB = comb[i0 + k + 1];
        const float4 wA = __ldcs(&Wb[(size_t)(i0 + k)     * (EMBED / 4) + lane]);
        const float4 wB = __ldcs(&Wb[(size_t)(i0 + k + 1) * (EMBED / 4) + lane]);
        accA.x = fmaf(cA, wA.x, accA.x); accA.y = fmaf(cA, wA.y, accA.y);
        accA.z = fmaf(cA, wA.z, accA.z); accA.w = fmaf(cA, wA.w, accA.w);
        accB.x = fmaf(cB, wB.x, accB.x); accB.y = fmaf(cB, wB.y, accB.y);
        accB.z = fmaf(cB, wB.z, accB.z); accB.w = fmaf(cB, wB.w, accB.w);
    }

    float4 acc;
    acc.x = accA.x + accB.x;
    acc.y = accA.y + accB.y;
    acc.z = accA.z + accB.z;
    acc.w = accA.w + accB.w;

    // stash per-warp partials
    reinterpret_cast<float4*>(&part[warp][0])[lane] = acc;
    __syncthreads();

    // ---- reduce 4 warps, relu, store (coalesced 512B)
    const float v = part[0][t] + part[1][t] + part[2][t] + part[3][t];
    out[(size_t)b * EMBED + t] = fmaxf(v, 0.0f);
}

extern "C" void kernel_launch(void* const* d_in, const int* in_sizes, int n_in,
                              void* d_out, int out_size)
{
    const float* features = (const float*)d_in[0];
    const float* weight   = (const float*)d_in[1];
    const int*   nodes    = (const int*)d_in[2];
    const int*   neigh    = (const int*)d_in[3];
    float*       out      = (float*)d_out;

    const int batch = in_sizes[2];      // 4096 (nodes element count)
    encoder_kernel<<<batch, 128>>>(features, weight, nodes, neigh, out);
}